// round 12
// baseline (speedup 1.0000x reference)
#include <cuda_runtime.h>
#include <cuda_fp16.h>
#include <cstdint>

// Problem constants
#define BB 32
#define NN 64
#define EE 4032
#define EPN 63
#define FI 4
#define NSTEP 10

// ---------------- scratch (device globals) ----------------------------------
__device__ float g_xst[BB * NN * FI];
__device__ float g_xarg[BB * NN * FI];
__device__ float g_kacc[BB * NN * FI];
__device__ float g_agg[BB * NN * 256];
// W2 split to fp16 hi/lo, pre-transposed: [k][ck][n][32 j]
__device__ __half g_w2h[2 * 256 * 256];
__device__ __half g_w2l[2 * 256 * 256];
// node weights transposed: [col][j]
__device__ float g_wo1t[256 * 264];
__device__ float g_wo2t[256 * 256];

// ---------------- smem layout (bytes) ----------------------------------------
#define SM_PRE   0         // 128 x 8 f32             (4096)
#define SM_EW    4096      // 128 x 2 f32             (1024)
#define SM_B1    5120      // 2 x 256 f32             (2048)
#define SM_B2    7168      // 2 x 256 f32             (2048)
#define SM_W1    9216      // 2 x 8 x 256 f32         (16384)
#define SM_PART  25600     // 2k x 4wm x 128 f32      (4096)
#define SM_A     29696     // 2 bufs x 128 rows x 144B (36864)
#define SM_B     66560     // 2 bufs x 2 limb x 128 rows x 80B (40960)
#define SMEM_TOT 107520

#define ABUF_BYTES 18432      // 128*144
#define BBUF_BYTES 20480      // 2*128*80
#define BREG_BYTES 10240      // 128*80

// ---------------- PTX helpers -------------------------------------------------
__device__ __forceinline__ uint32_t smem_u32(const void* p) {
    uint32_t a;
    asm("{ .reg .u64 t; cvta.to.shared.u64 t, %1; cvt.u32.u64 %0, t; }"
        : "=r"(a) : "l"(p));
    return a;
}
#define CP_ASYNC16(dst, src) \
    asm volatile("cp.async.cg.shared.global [%0], [%1], 16;" :: "r"(dst), "l"(src))
#define CP_COMMIT() asm volatile("cp.async.commit_group;" ::: "memory")
#define CP_WAIT1()  asm volatile("cp.async.wait_group 1;" ::: "memory")
#define CP_WAIT0()  asm volatile("cp.async.wait_group 0;" ::: "memory")

#define LDSM_X4(r0, r1, r2, r3, addr)                                        \
    asm volatile("ldmatrix.sync.aligned.m8n8.x4.shared.b16 {%0,%1,%2,%3}, [%4];" \
        : "=r"(r0), "=r"(r1), "=r"(r2), "=r"(r3) : "r"(addr))

// f32-accumulator MMA (main term)
#define MMA_F16(d, a, b0, b1)                                                \
    asm volatile("mma.sync.aligned.m16n8k16.row.col.f32.f16.f16.f32 "        \
        "{%0,%1,%2,%3}, {%4,%5,%6,%7}, {%8,%9}, {%0,%1,%2,%3};"              \
        : "+f"((d)[0]), "+f"((d)[1]), "+f"((d)[2]), "+f"((d)[3])             \
        : "r"((a)[0]), "r"((a)[1]), "r"((a)[2]), "r"((a)[3]),                \
          "r"(b0), "r"(b1))

// f16-accumulator MMA (correction terms, full-rate)
#define MMA_F16ACC(d, a, b0, b1)                                             \
    asm volatile("mma.sync.aligned.m16n8k16.row.col.f16.f16.f16.f16 "       \
        "{%0,%1}, {%2,%3,%4,%5}, {%6,%7}, {%0,%1};"                          \
        : "+r"((d)[0]), "+r"((d)[1])                                         \
        : "r"((a)[0]), "r"((a)[1]), "r"((a)[2]), "r"((a)[3]),                \
          "r"(b0), "r"(b1))

// ---------------- init / prep ---------------------------------------------------
__global__ void init_kernel(const float* __restrict__ inputs)
{
    int i = blockIdx.x * blockDim.x + threadIdx.x;
    if (i < BB * NN * FI) {
        int f = i & 3;
        int row = i >> 2;
        float v = inputs[row * (11 * FI) + f];
        g_xst[i] = v;
        g_xarg[i] = v;
    }
}

__global__ void w2split_kernel(const float* __restrict__ W2)
{
    int i = blockIdx.x * blockDim.x + threadIdx.x;   // 131072
    int k = i >> 16;
    int hid = (i >> 8) & 255;
    int n = i & 255;
    float w = W2[i];
    __half ah = __float2half_rn(w);
    __half al = __float2half_rn(w - __half2float(ah));
    int ck = hid >> 5, j = hid & 31;
    size_t dst = ((size_t)(k * 8 + ck) * 256 + n) * 32 + j;
    g_w2h[dst] = ah;
    g_w2l[dst] = al;
}

__global__ void wo_transpose_kernel(const float* __restrict__ Wo1,
                                    const float* __restrict__ Wo2)
{
    int i = blockIdx.x * blockDim.x + threadIdx.x;
    if (i < 256 * 264) {
        int col = i / 264, j = i % 264;
        g_wo1t[col * 264 + j] = (j < 260) ? Wo1[j * 256 + col] : 0.f;
    }
    if (i < 256 * 256) {
        int col = i >> 8, j = i & 255;
        g_wo2t[col * 256 + j] = Wo2[j * 256 + col];
    }
}

// ---------------- edge kernel: split mma, corrections in f16 accumulators --------
// CTA = (batch, 2 receivers, N-half). M=128 rows, N=128 cols, K=256 (x2 k-comp),
// 16 chunks of 32 hidden. Main term f32-acc, two correction terms share one
// f16 accumulator set. 8 warps = 4 M-warps (32 rows) x 2 N-warps (64 cols).
__global__ __launch_bounds__(256, 1) void edge_mma_kernel(
    const float* __restrict__ edges,
    const float* __restrict__ W1g, const float* __restrict__ b1g,
    const float* __restrict__ b2g)
{
    extern __shared__ float s[];
    uint32_t sb = smem_u32(s);
    const int t = threadIdx.x;
    const int wid = t >> 5, lane = t & 31;
    const int group = lane >> 2, tid4 = lane & 3;
    const int wm = wid & 3, wn = wid >> 2;          // 4 M-warps x 2 N-warps
    const int b = blockIdx.x >> 6;
    const int sub = blockIdx.x & 63;
    const int n0 = (sub >> 1) * 2;                  // receiver tile
    const int nh = sub & 1;                         // N half: cols nh*128..+127

    // ---- stage constants
    for (int i = t; i < 512; i += 256) {
        s[SM_B1 / 4 + i] = b1g[i];
        s[SM_B2 / 4 + i] = b2g[i];
    }
    for (int i = t; i < 4096; i += 256) s[SM_W1 / 4 + i] = W1g[i];
    if (t < 128) {
        int g = t >> 6, n = n0 + g, el = t & 63;
        float4 xs = make_float4(0.f, 0.f, 0.f, 0.f), xr = xs;
        float2 ew = make_float2(0.f, 0.f);
        if (el < EPN) {
            int send = (el < n) ? el : el + 1;
            xs = *(const float4*)(g_xarg + (b * NN + send) * 4);
            xr = *(const float4*)(g_xarg + (b * NN + n) * 4);
            ew = *(const float2*)(edges + ((long)(b * EE) + n * EPN + el) * 2);
        }
        float4* pr = (float4*)(s + SM_PRE / 4 + t * 8);
        pr[0] = xs; pr[1] = xr;
        s[SM_EW / 4 + t * 2 + 0] = ew.x;
        s[SM_EW / 4 + t * 2 + 1] = ew.y;
    }
    __syncthreads();

    // ---- staging helpers
    auto stage_w2 = [&](int c, int buf) {
        int k = c >> 3, ck = c & 7;
        size_t off = ((size_t)(k * 8 + ck) * 256 + nh * 128) * 32;
        const char* srch = (const char*)(g_w2h + off);
        const char* srcl = (const char*)(g_w2l + off);
        uint32_t db = sb + SM_B + (uint32_t)buf * BBUF_BYTES;
        #pragma unroll
        for (int i = 0; i < 2; i++) {
            int idx = t + i * 256;            // 0..511
            int row = idx >> 2, seg = idx & 3;
            uint32_t doff = (uint32_t)(row * 80 + seg * 16);
            uint32_t soff = (uint32_t)(row * 64 + seg * 16);
            CP_ASYNC16(db + doff, srch + soff);
            CP_ASYNC16(db + BREG_BYTES + doff, srcl + soff);
        }
    };
    auto compute_h = [&](int c, int buf) {
        int k = c >> 3, ck = c & 7;
        int jp = t & 15, rg = t >> 4;
        int j0 = ck * 32 + 2 * jp;
        float w1a[8], w1b[8];
        #pragma unroll
        for (int f = 0; f < 8; f++) {
            w1a[f] = s[SM_W1 / 4 + (k * 8 + f) * 256 + j0];
            w1b[f] = s[SM_W1 / 4 + (k * 8 + f) * 256 + j0 + 1];
        }
        float b1a = s[SM_B1 / 4 + k * 256 + j0];
        float b1b = s[SM_B1 / 4 + k * 256 + j0 + 1];
        char* ab = (char*)s + SM_A + buf * ABUF_BYTES + jp * 4;
        #pragma unroll
        for (int rr = 0; rr < 8; rr++) {
            int r = rg * 8 + rr;
            const float4* pr = (const float4*)(s + SM_PRE / 4 + r * 8);
            float4 p0 = pr[0], p1 = pr[1];
            float h0 = b1a, h1 = b1b;
            h0 += p0.x * w1a[0]; h1 += p0.x * w1b[0];
            h0 += p0.y * w1a[1]; h1 += p0.y * w1b[1];
            h0 += p0.z * w1a[2]; h1 += p0.z * w1b[2];
            h0 += p0.w * w1a[3]; h1 += p0.w * w1b[3];
            h0 += p1.x * w1a[4]; h1 += p1.x * w1b[4];
            h0 += p1.y * w1a[5]; h1 += p1.y * w1b[5];
            h0 += p1.z * w1a[6]; h1 += p1.z * w1b[6];
            h0 += p1.w * w1a[7]; h1 += p1.w * w1b[7];
            h0 = fmaxf(h0, 0.f); h1 = fmaxf(h1, 0.f);
            __half ah0 = __float2half_rn(h0);
            __half ah1 = __float2half_rn(h1);
            __half al0 = __float2half_rn(h0 - __half2float(ah0));
            __half al1 = __float2half_rn(h1 - __half2float(ah1));
            __half2 hi = __halves2half2(ah0, ah1);
            __half2 lo = __halves2half2(al0, al1);
            *(uint32_t*)(ab + r * 144)      = *(uint32_t*)&hi;
            *(uint32_t*)(ab + r * 144 + 64) = *(uint32_t*)&lo;
        }
    };

    float acc[2][8][4];            // main, f32
    uint32_t corr[2][8][2];        // corrections, f16x2 pairs
    #pragma unroll
    for (int m = 0; m < 2; m++)
        #pragma unroll
        for (int nt = 0; nt < 8; nt++) {
            #pragma unroll
            for (int q = 0; q < 4; q++) acc[m][nt][q] = 0.f;
            corr[m][nt][0] = 0u; corr[m][nt][1] = 0u;
        }

    // per-thread invariant fragment base addresses
    const uint32_t aRow = sb + SM_A + (uint32_t)(wm * 32 + (lane & 15)) * 144u
                        + ((lane & 16) ? 16u : 0u);
    const uint32_t bRow = sb + SM_B
                        + (uint32_t)(wn * 64 + (lane & 7) + ((lane >> 4) & 1) * 8) * 80u
                        + (uint32_t)((lane >> 3) & 1) * 16u;

    // prologue: chunk 0
    stage_w2(0, 0);
    CP_COMMIT();
    compute_h(0, 0);

    for (int c = 0; c < 16; c++) {
        int buf = c & 1;
        if (c < 15) {
            stage_w2(c + 1, 1 - buf);
            CP_COMMIT();
            compute_h(c + 1, 1 - buf);
            CP_WAIT1();
        } else {
            CP_WAIT0();
        }
        __syncthreads();

        const uint32_t aBuf = (uint32_t)buf * ABUF_BYTES;
        const uint32_t bBuf = (uint32_t)buf * BBUF_BYTES;

        // ---- split mma over chunk c: 2 k16 slices x 3 terms
        #pragma unroll
        for (int kk = 0; kk < 2; kk++) {
            uint32_t aH[2][4], aL[2][4];
            uint32_t aoffH = aRow + aBuf + (uint32_t)kk * 32u;
            #pragma unroll
            for (int mt = 0; mt < 2; mt++) {
                LDSM_X4(aH[mt][0], aH[mt][1], aH[mt][2], aH[mt][3],
                        aoffH + (uint32_t)mt * (16u * 144u));
                LDSM_X4(aL[mt][0], aL[mt][1], aL[mt][2], aL[mt][3],
                        aoffH + 64u + (uint32_t)mt * (16u * 144u));
            }
            uint32_t bbase = bRow + bBuf + (uint32_t)kk * 32u;
            #pragma unroll
            for (int ntp = 0; ntp < 4; ntp++) {
                uint32_t bh0, bh1, bh2, bh3, bl0, bl1, bl2, bl3;
                LDSM_X4(bh0, bh1, bh2, bh3, bbase + (uint32_t)ntp * 1280u);
                LDSM_X4(bl0, bl1, bl2, bl3,
                        bbase + BREG_BYTES + (uint32_t)ntp * 1280u);
                #pragma unroll
                for (int mt = 0; mt < 2; mt++) {
                    // main term: f32 accumulators
                    MMA_F16(acc[mt][2 * ntp],     aH[mt], bh0, bh1);
                    MMA_F16(acc[mt][2 * ntp + 1], aH[mt], bh2, bh3);
                    // corrections: shared f16 accumulators (full rate)
                    MMA_F16ACC(corr[mt][2 * ntp],     aL[mt], bh0, bh1);
                    MMA_F16ACC(corr[mt][2 * ntp + 1], aL[mt], bh2, bh3);
                    MMA_F16ACC(corr[mt][2 * ntp],     aH[mt], bl0, bl1);
                    MMA_F16ACC(corr[mt][2 * ntp + 1], aH[mt], bl2, bl3);
                }
            }
        }

        // ---- epilogue for this k-component after its last chunk
        if ((c & 7) == 7) {
            int k = c >> 3;
            float colsum[16];
            #pragma unroll
            for (int i = 0; i < 16; i++) colsum[i] = 0.f;
            #pragma unroll
            for (int m = 0; m < 2; m++) {
                int rbase = wm * 32 + m * 16 + group;
                float ew0 = s[SM_EW / 4 + rbase * 2 + k];
                float ew1 = s[SM_EW / 4 + (rbase + 8) * 2 + k];
                #pragma unroll
                for (int nt = 0; nt < 8; nt++) {
                    __half2 p0 = *(__half2*)&corr[m][nt][0];
                    __half2 p1 = *(__half2*)&corr[m][nt][1];
                    float v0 = acc[m][nt][0] + __low2float(p0);
                    float v1 = acc[m][nt][1] + __high2float(p0);
                    float v2 = acc[m][nt][2] + __low2float(p1);
                    float v3 = acc[m][nt][3] + __high2float(p1);
                    int col0 = nh * 128 + wn * 64 + nt * 8 + tid4 * 2;
                    float bz0 = s[SM_B2 / 4 + k * 256 + col0];
                    float bz1 = s[SM_B2 / 4 + k * 256 + col0 + 1];
                    colsum[nt * 2 + 0] += fmaxf(v0 + bz0, 0.f) * ew0
                                        + fmaxf(v2 + bz0, 0.f) * ew1;
                    colsum[nt * 2 + 1] += fmaxf(v1 + bz1, 0.f) * ew0
                                        + fmaxf(v3 + bz1, 0.f) * ew1;
                }
            }
            #pragma unroll
            for (int off = 4; off <= 16; off <<= 1)
                #pragma unroll
                for (int i = 0; i < 16; i++)
                    colsum[i] += __shfl_xor_sync(0xffffffffu, colsum[i], off);
            if (lane < 4) {
                float* dst = s + SM_PART / 4 + (k * 4 + wm) * 128 + wn * 64;
                #pragma unroll
                for (int nt = 0; nt < 8; nt++) {
                    dst[nt * 8 + lane * 2 + 0] = colsum[nt * 2 + 0];
                    dst[nt * 8 + lane * 2 + 1] = colsum[nt * 2 + 1];
                }
            }
            #pragma unroll
            for (int m = 0; m < 2; m++)
                #pragma unroll
                for (int nt = 0; nt < 8; nt++) {
                    #pragma unroll
                    for (int q = 0; q < 4; q++) acc[m][nt][q] = 0.f;
                    corr[m][nt][0] = 0u; corr[m][nt][1] = 0u;
                }
        }
        __syncthreads();
    }

    // ---- final aggregation across k and M-warps (2 receivers x 128 cols)
    {
        const float* p = s + SM_PART / 4;
        int recv = t >> 7, col = t & 127;
        float v = p[(recv * 2 + 0) * 128 + col] + p[(recv * 2 + 1) * 128 + col]
                + p[(4 + recv * 2 + 0) * 128 + col] + p[(4 + recv * 2 + 1) * 128 + col];
        g_agg[(b * NN + n0 + recv) * 256 + nh * 128 + col] = v;
    }
}

// ---------------- node kernel: output MLP + RK4, vectorized transposed weights --
#define NROWS 16
__global__ __launch_bounds__(256) void node_kernel(
    const float* __restrict__ bo1, const float* __restrict__ bo2,
    const float* __restrict__ Wo3, const float* __restrict__ bo3,
    float* __restrict__ outp, int stage, int step)
{
    __shared__ float s_a[NROWS][264];   // aug, later reused as h2
    __shared__ float s_h[NROWS][264];

    int r0 = blockIdx.x * NROWS;
    int t = threadIdx.x;

    for (int i = t; i < NROWS * 264; i += 256) {
        int r = i / 264, c = i % 264;
        int row = r0 + r;
        float v = 0.f;
        if (c < 4) v = g_xarg[row * 4 + c];
        else if (c < 260) v = g_agg[row * 256 + (c - 4)];
        s_a[r][c] = v;
    }
    __syncthreads();

    float acc[NROWS];

    // ---- layer 1: K=264 (zero-padded), 66 float4 steps, depth-2 prefetch
    {
        float bv = bo1[t];
        #pragma unroll
        for (int r = 0; r < NROWS; r++) acc[r] = bv;
    }
    {
        const float4* wrow = (const float4*)(g_wo1t + t * 264);
        float4 w0 = __ldg(&wrow[0]);
        float4 w1 = __ldg(&wrow[1]);
        #pragma unroll 2
        for (int it = 0; it < 66; it++) {
            float4 cw = (it & 1) ? w1 : w0;
            int jn = it + 2;
            if (jn < 66) {
                if (it & 1) w1 = __ldg(&wrow[jn]);
                else        w0 = __ldg(&wrow[jn]);
            }
            int j = it * 4;
            #pragma unroll
            for (int r = 0; r < NROWS; r++) {
                float4 a4 = *(const float4*)&s_a[r][j];
                acc[r] += a4.x * cw.x + a4.y * cw.y + a4.z * cw.z + a4.w * cw.w;
            }
        }
    }
    #pragma unroll
    for (int r = 0; r < NROWS; r++) s_h[r][t] = fmaxf(acc[r], 0.f);
    __syncthreads();

    // ---- layer 2: K=256, 64 float4 steps, depth-2 prefetch
    {
        float bv = bo2[t];
        #pragma unroll
        for (int r = 0; r < NROWS; r++) acc[r] = bv;
    }
    {
        const float4* wrow = (const float4*)(g_wo2t + t * 256);
        float4 w0 = __ldg(&wrow[0]);
        float4 w1 = __ldg(&wrow[1]);
        #pragma unroll 2
        for (int it = 0; it < 64; it++) {
            float4 cw = (it & 1) ? w1 : w0;
            int jn = it + 2;
            if (jn < 64) {
                if (it & 1) w1 = __ldg(&wrow[jn]);
                else        w0 = __ldg(&wrow[jn]);
            }
            int j = it * 4;
            #pragma unroll
            for (int r = 0; r < NROWS; r++) {
                float4 a4 = *(const float4*)&s_h[r][j];
                acc[r] += a4.x * cw.x + a4.y * cw.y + a4.z * cw.z + a4.w * cw.w;
            }
        }
    }
    __syncthreads();
    #pragma unroll
    for (int r = 0; r < NROWS; r++) s_a[r][t] = fmaxf(acc[r], 0.f);   // h2
    __syncthreads();

    // final 256->4 projection: warp w handles rows 2w, 2w+1
    int wr = t >> 5, lane = t & 31;
    #pragma unroll
    for (int rr = 0; rr < 2; rr++) {
        int rl = wr * 2 + rr;
        float4 pf = make_float4(0.f, 0.f, 0.f, 0.f);
        for (int j = lane; j < 256; j += 32) {
            float v = s_a[rl][j];
            float4 w3 = *(const float4*)(Wo3 + j * 4);
            pf.x += v * w3.x; pf.y += v * w3.y;
            pf.z += v * w3.z; pf.w += v * w3.w;
        }
        #pragma unroll
        for (int off = 16; off; off >>= 1) {
            pf.x += __shfl_xor_sync(0xffffffffu, pf.x, off);
            pf.y += __shfl_xor_sync(0xffffffffu, pf.y, off);
            pf.z += __shfl_xor_sync(0xffffffffu, pf.z, off);
            pf.w += __shfl_xor_sync(0xffffffffu, pf.w, off);
        }

        if (lane == 0) {
            int row = r0 + rl;
            float dt = (float)(step + 1) / 10.0f - (float)step / 10.0f;

            float4 xa = *(const float4*)(g_xarg + row * 4);
            float4 xs = *(const float4*)(g_xst + row * 4);

            float4 ko;
            ko.x = xa.x + pf.x + bo3[0];
            ko.y = xa.y + pf.y + bo3[1];
            ko.z = xa.z + pf.z + bo3[2];
            ko.w = xa.w + pf.w + bo3[3];

            float4 ka;
            if (stage == 0) {
                ka = ko;
            } else {
                ka = *(const float4*)(g_kacc + row * 4);
                float sc = (stage == 3) ? 1.0f : 2.0f;
                ka.x += sc * ko.x; ka.y += sc * ko.y;
                ka.z += sc * ko.z; ka.w += sc * ko.w;
            }

            if (stage < 3) {
                *(float4*)(g_kacc + row * 4) = ka;
                float cc = (stage == 2) ? dt : 0.5f * dt;
                float4 xn;
                xn.x = xs.x + cc * ko.x; xn.y = xs.y + cc * ko.y;
                xn.z = xs.z + cc * ko.z; xn.w = xs.w + cc * ko.w;
                *(float4*)(g_xarg + row * 4) = xn;
            } else {
                float cc = dt * (1.0f / 6.0f);
                float4 xn;
                xn.x = xs.x + cc * ka.x; xn.y = xs.y + cc * ka.y;
                xn.z = xs.z + cc * ka.z; xn.w = xs.w + cc * ka.w;
                *(float4*)(g_xst + row * 4) = xn;
                *(float4*)(g_xarg + row * 4) = xn;
                *(float4*)(outp + (row * NSTEP + step) * 4) = xn;
            }
        }
    }
}

// ---------------- launch ------------------------------------------------------
extern "C" void kernel_launch(void* const* d_in, const int* in_sizes, int n_in,
                              void* d_out, int out_size)
{
    const float* inputs = (const float*)d_in[0];
    const float* edges  = (const float*)d_in[1];
    const float* W1  = (const float*)d_in[4];
    const float* b1  = (const float*)d_in[5];
    const float* W2  = (const float*)d_in[6];
    const float* b2  = (const float*)d_in[7];
    const float* Wo1 = (const float*)d_in[8];
    const float* bo1 = (const float*)d_in[9];
    const float* Wo2 = (const float*)d_in[10];
    const float* bo2 = (const float*)d_in[11];
    const float* Wo3 = (const float*)d_in[12];
    const float* bo3 = (const float*)d_in[13];
    float* outp = (float*)d_out;

    cudaFuncSetAttribute(edge_mma_kernel,
                         cudaFuncAttributeMaxDynamicSharedMemorySize, SMEM_TOT);

    init_kernel<<<(BB * NN * FI + 255) / 256, 256>>>(inputs);
    w2split_kernel<<<(2 * 256 * 256) / 256, 256>>>(W2);
    wo_transpose_kernel<<<(256 * 264 + 255) / 256, 256>>>(Wo1, Wo2);

    for (int step = 0; step < NSTEP; step++) {
        for (int stage = 0; stage < 4; stage++) {
            edge_mma_kernel<<<BB * 64, 256, SMEM_TOT>>>(edges, W1, b1, b2);
            node_kernel<<<BB * NN / NROWS, 256>>>(bo1, bo2, Wo3, bo3,
                                                  outp, stage, step);
        }
    }
}

// round 13
// speedup vs baseline: 1.2108x; 1.2108x over previous
#include <cuda_runtime.h>
#include <cuda_fp16.h>
#include <cstdint>

// Problem constants
#define BB 32
#define NN 64
#define EE 4032
#define EPN 63
#define FI 4
#define NSTEP 10

// ---------------- scratch (device globals) ----------------------------------
__device__ float g_xst[BB * NN * FI];
__device__ float g_xarg[BB * NN * FI];
__device__ float g_kacc[BB * NN * FI];
__device__ float g_agg[BB * NN * 256];
// W2 split to fp16 hi/lo, pre-transposed: [k][ck][n][32 j]
__device__ __half g_w2h[2 * 256 * 256];
__device__ __half g_w2l[2 * 256 * 256];
// node weights transposed: [col][j]
__device__ float g_wo1t[256 * 264];
__device__ float g_wo2t[256 * 256];

// ---------------- smem layout (bytes) — R8 edge config ------------------------
#define SM_PRE   0        // 128 x 8 f32            (4096)
#define SM_EW    4096     // 128 x 2 f32            (1024)
#define SM_B1    5120     // 2 x 256 f32            (2048)
#define SM_B2    7168     // 2 x 256 f32            (2048)
#define SM_W1    9216     // 2 x 8 x 256 f32        (16384)
#define SM_PART  25600    // 2 x 4 x 128 f32        (4096)
#define SM_A     29696    // 2 bufs x 128 rows x 144B (36864)
#define SM_B     66560    // 2 bufs x 2 limb x 128 rows x 80B (40960)
#define SMEM_TOT 107520

#define ABUF_BYTES 18432      // 128*144
#define BBUF_BYTES 20480      // 2*128*80
#define BREG_BYTES 10240      // 128*80

// ---------------- PTX helpers -------------------------------------------------
__device__ __forceinline__ uint32_t smem_u32(const void* p) {
    uint32_t a;
    asm("{ .reg .u64 t; cvta.to.shared.u64 t, %1; cvt.u32.u64 %0, t; }"
        : "=r"(a) : "l"(p));
    return a;
}
#define CP_ASYNC16(dst, src) \
    asm volatile("cp.async.cg.shared.global [%0], [%1], 16;" :: "r"(dst), "l"(src))
#define CP_COMMIT() asm volatile("cp.async.commit_group;" ::: "memory")
#define CP_WAIT1()  asm volatile("cp.async.wait_group 1;" ::: "memory")
#define CP_WAIT0()  asm volatile("cp.async.wait_group 0;" ::: "memory")

#define LDSM_X4(r0, r1, r2, r3, addr)                                        \
    asm volatile("ldmatrix.sync.aligned.m8n8.x4.shared.b16 {%0,%1,%2,%3}, [%4];" \
        : "=r"(r0), "=r"(r1), "=r"(r2), "=r"(r3) : "r"(addr))

#define MMA_F16(d, a, b0, b1)                                                \
    asm volatile("mma.sync.aligned.m16n8k16.row.col.f32.f16.f16.f32 "        \
        "{%0,%1,%2,%3}, {%4,%5,%6,%7}, {%8,%9}, {%0,%1,%2,%3};"              \
        : "+f"((d)[0]), "+f"((d)[1]), "+f"((d)[2]), "+f"((d)[3])             \
        : "r"((a)[0]), "r"((a)[1]), "r"((a)[2]), "r"((a)[3]),                \
          "r"(b0), "r"(b1))

// ---------------- init / prep ---------------------------------------------------
__global__ void init_kernel(const float* __restrict__ inputs)
{
    int i = blockIdx.x * blockDim.x + threadIdx.x;
    if (i < BB * NN * FI) {
        int f = i & 3;
        int row = i >> 2;
        float v = inputs[row * (11 * FI) + f];
        g_xst[i] = v;
        g_xarg[i] = v;
    }
}

__global__ void w2split_kernel(const float* __restrict__ W2)
{
    int i = blockIdx.x * blockDim.x + threadIdx.x;   // 131072
    int k = i >> 16;
    int hid = (i >> 8) & 255;
    int n = i & 255;
    float w = W2[i];
    __half ah = __float2half_rn(w);
    __half al = __float2half_rn(w - __half2float(ah));
    int ck = hid >> 5, j = hid & 31;
    size_t dst = ((size_t)(k * 8 + ck) * 256 + n) * 32 + j;
    g_w2h[dst] = ah;
    g_w2l[dst] = al;
}

__global__ void wo_transpose_kernel(const float* __restrict__ Wo1,
                                    const float* __restrict__ Wo2)
{
    int i = blockIdx.x * blockDim.x + threadIdx.x;
    if (i < 256 * 264) {
        int col = i / 264, j = i % 264;
        g_wo1t[col * 264 + j] = (j < 260) ? Wo1[j * 256 + col] : 0.f;
    }
    if (i < 256 * 256) {
        int col = i >> 8, j = i & 255;
        g_wo2t[col * 256 + j] = Wo2[j * 256 + col];
    }
}

// ---------------- edge kernel: R8 config (measured 308 us) ----------------------
// CTA = (batch, 2 receivers, N-half). M=128 edge rows, N=128 of 256 outputs,
// K=256 hidden (x2 k-comp), 16 chunks of 32; chunk = eff K96 fp16 3-term split.
// 2 CTAs per SM for latency hiding.
__global__ __launch_bounds__(256, 2) void edge_mma_kernel(
    const float* __restrict__ edges,
    const float* __restrict__ W1g, const float* __restrict__ b1g,
    const float* __restrict__ b2g)
{
    extern __shared__ float s[];
    uint32_t sb = smem_u32(s);
    const int t = threadIdx.x;
    const int wid = t >> 5, lane = t & 31;
    const int group = lane >> 2, tid4 = lane & 3;
    const int wm = wid & 3, wn = wid >> 2;          // 4 M-warps x 2 N-warps
    const int b = blockIdx.x >> 6;
    const int sub = blockIdx.x & 63;
    const int n0 = (sub >> 1) * 2;                  // receiver tile
    const int nh = sub & 1;                         // N half: cols nh*128..+127

    // ---- stage constants
    for (int i = t; i < 512; i += 256) {
        s[SM_B1 / 4 + i] = b1g[i];
        s[SM_B2 / 4 + i] = b2g[i];
    }
    for (int i = t; i < 4096; i += 256) s[SM_W1 / 4 + i] = W1g[i];
    if (t < 128) {
        int g = t >> 6, n = n0 + g, el = t & 63;
        float4 xs = make_float4(0.f, 0.f, 0.f, 0.f), xr = xs;
        float2 ew = make_float2(0.f, 0.f);
        if (el < EPN) {
            int send = (el < n) ? el : el + 1;
            xs = *(const float4*)(g_xarg + (b * NN + send) * 4);
            xr = *(const float4*)(g_xarg + (b * NN + n) * 4);
            ew = *(const float2*)(edges + ((long)(b * EE) + n * EPN + el) * 2);
        }
        float4* pr = (float4*)(s + SM_PRE / 4 + t * 8);
        pr[0] = xs; pr[1] = xr;
        s[SM_EW / 4 + t * 2 + 0] = ew.x;
        s[SM_EW / 4 + t * 2 + 1] = ew.y;
    }
    __syncthreads();

    // ---- staging helpers
    auto stage_w2 = [&](int c, int buf) {
        int k = c >> 3, ck = c & 7;
        size_t off = ((size_t)(k * 8 + ck) * 256 + nh * 128) * 32;
        const char* srch = (const char*)(g_w2h + off);
        const char* srcl = (const char*)(g_w2l + off);
        uint32_t db = sb + SM_B + (uint32_t)buf * BBUF_BYTES;
        #pragma unroll
        for (int i = 0; i < 2; i++) {
            int idx = t + i * 256;            // 0..511
            int row = idx >> 2, seg = idx & 3;
            uint32_t doff = (uint32_t)(row * 80 + seg * 16);
            uint32_t soff = (uint32_t)(row * 64 + seg * 16);
            CP_ASYNC16(db + doff, srch + soff);
            CP_ASYNC16(db + BREG_BYTES + doff, srcl + soff);
        }
    };
    auto compute_h = [&](int c, int buf) {
        int k = c >> 3, ck = c & 7;
        int jp = t & 15, rg = t >> 4;
        int j0 = ck * 32 + 2 * jp;
        float w1a[8], w1b[8];
        #pragma unroll
        for (int f = 0; f < 8; f++) {
            w1a[f] = s[SM_W1 / 4 + (k * 8 + f) * 256 + j0];
            w1b[f] = s[SM_W1 / 4 + (k * 8 + f) * 256 + j0 + 1];
        }
        float b1a = s[SM_B1 / 4 + k * 256 + j0];
        float b1b = s[SM_B1 / 4 + k * 256 + j0 + 1];
        char* ab = (char*)s + SM_A + buf * ABUF_BYTES + jp * 4;
        #pragma unroll
        for (int rr = 0; rr < 8; rr++) {
            int r = rg * 8 + rr;
            const float4* pr = (const float4*)(s + SM_PRE / 4 + r * 8);
            float4 p0 = pr[0], p1 = pr[1];
            float h0 = b1a, h1 = b1b;
            h0 += p0.x * w1a[0]; h1 += p0.x * w1b[0];
            h0 += p0.y * w1a[1]; h1 += p0.y * w1b[1];
            h0 += p0.z * w1a[2]; h1 += p0.z * w1b[2];
            h0 += p0.w * w1a[3]; h1 += p0.w * w1b[3];
            h0 += p1.x * w1a[4]; h1 += p1.x * w1b[4];
            h0 += p1.y * w1a[5]; h1 += p1.y * w1b[5];
            h0 += p1.z * w1a[6]; h1 += p1.z * w1b[6];
            h0 += p1.w * w1a[7]; h1 += p1.w * w1b[7];
            h0 = fmaxf(h0, 0.f); h1 = fmaxf(h1, 0.f);
            __half ah0 = __float2half_rn(h0);
            __half ah1 = __float2half_rn(h1);
            __half al0 = __float2half_rn(h0 - __half2float(ah0));
            __half al1 = __float2half_rn(h1 - __half2float(ah1));
            __half2 hi = __halves2half2(ah0, ah1);
            __half2 lo = __halves2half2(al0, al1);
            *(uint32_t*)(ab + r * 144)      = *(uint32_t*)&hi;
            *(uint32_t*)(ab + r * 144 + 64) = *(uint32_t*)&lo;
        }
    };

    float acc[2][8][4];
    #pragma unroll
    for (int m = 0; m < 2; m++)
        #pragma unroll
        for (int nt = 0; nt < 8; nt++)
            #pragma unroll
            for (int q = 0; q < 4; q++) acc[m][nt][q] = 0.f;

    // per-thread invariant fragment addresses
    const uint32_t aRow = sb + SM_A + (uint32_t)(wm * 32 + (lane & 15)) * 144u
                        + ((lane & 16) ? 16u : 0u);
    const uint32_t bRow = sb + SM_B
                        + (uint32_t)(wn * 64 + (lane & 7) + ((lane >> 4) & 1) * 8) * 80u
                        + (uint32_t)((lane >> 3) & 1) * 16u;

    // prologue: chunk 0
    stage_w2(0, 0);
    CP_COMMIT();
    compute_h(0, 0);

    for (int c = 0; c < 16; c++) {
        int buf = c & 1;
        if (c < 15) {
            stage_w2(c + 1, 1 - buf);
            CP_COMMIT();
            compute_h(c + 1, 1 - buf);
            CP_WAIT1();
        } else {
            CP_WAIT0();
        }
        __syncthreads();

        // ---- fp16 split mma over chunk c: 6 eff k16-steps
        #pragma unroll
        for (int ks = 0; ks < 6; ks++) {
            uint32_t aoff = (uint32_t)buf * ABUF_BYTES
                          + ((ks < 4) ? 0u : 64u) + (uint32_t)(ks & 1) * 32u;
            uint32_t a[2][4];
            LDSM_X4(a[0][0], a[0][1], a[0][2], a[0][3], aRow + aoff);
            LDSM_X4(a[1][0], a[1][1], a[1][2], a[1][3], aRow + aoff + 16u * 144u);
            uint32_t boff = (uint32_t)buf * BBUF_BYTES
                          + ((ks == 2 || ks == 3) ? (uint32_t)BREG_BYTES : 0u)
                          + (uint32_t)(ks & 1) * 32u;
            uint32_t bbase = bRow + boff;
            #pragma unroll
            for (int ntp = 0; ntp < 4; ntp++) {
                uint32_t b0, b1, b2, b3;
                LDSM_X4(b0, b1, b2, b3, bbase + (uint32_t)ntp * 1280u);
                MMA_F16(acc[0][2 * ntp],     a[0], b0, b1);
                MMA_F16(acc[1][2 * ntp],     a[1], b0, b1);
                MMA_F16(acc[0][2 * ntp + 1], a[0], b2, b3);
                MMA_F16(acc[1][2 * ntp + 1], a[1], b2, b3);
            }
        }

        // ---- epilogue for this k-component after its last chunk
        if ((c & 7) == 7) {
            int k = c >> 3;
            float colsum[16];
            #pragma unroll
            for (int i = 0; i < 16; i++) colsum[i] = 0.f;
            #pragma unroll
            for (int m = 0; m < 2; m++) {
                int rbase = wm * 32 + m * 16 + group;
                float ew0 = s[SM_EW / 4 + rbase * 2 + k];
                float ew1 = s[SM_EW / 4 + (rbase + 8) * 2 + k];
                #pragma unroll
                for (int nt = 0; nt < 8; nt++) {
                    int col0 = nh * 128 + wn * 64 + nt * 8 + tid4 * 2;
                    float bz0 = s[SM_B2 / 4 + k * 256 + col0];
                    float bz1 = s[SM_B2 / 4 + k * 256 + col0 + 1];
                    colsum[nt * 2 + 0] += fmaxf(acc[m][nt][0] + bz0, 0.f) * ew0
                                        + fmaxf(acc[m][nt][2] + bz0, 0.f) * ew1;
                    colsum[nt * 2 + 1] += fmaxf(acc[m][nt][1] + bz1, 0.f) * ew0
                                        + fmaxf(acc[m][nt][3] + bz1, 0.f) * ew1;
                }
            }
            #pragma unroll
            for (int off = 4; off <= 16; off <<= 1)
                #pragma unroll
                for (int i = 0; i < 16; i++)
                    colsum[i] += __shfl_xor_sync(0xffffffffu, colsum[i], off);
            if (lane < 4) {
                float* dst = s + SM_PART / 4 + (k * 4 + wm) * 128 + wn * 64;
                #pragma unroll
                for (int nt = 0; nt < 8; nt++) {
                    dst[nt * 8 + lane * 2 + 0] = colsum[nt * 2 + 0];
                    dst[nt * 8 + lane * 2 + 1] = colsum[nt * 2 + 1];
                }
            }
            #pragma unroll
            for (int m = 0; m < 2; m++)
                #pragma unroll
                for (int nt = 0; nt < 8; nt++)
                    #pragma unroll
                    for (int q = 0; q < 4; q++) acc[m][nt][q] = 0.f;
        }
        __syncthreads();
    }

    // ---- final aggregation across k and M-warps (2 receivers x 128 cols)
    {
        const float* p = s + SM_PART / 4;
        int recv = t >> 7, col = t & 127;
        float v = p[(recv * 2 + 0) * 128 + col] + p[(recv * 2 + 1) * 128 + col]
                + p[(4 + recv * 2 + 0) * 128 + col] + p[(4 + recv * 2 + 1) * 128 + col];
        g_agg[(b * NN + n0 + recv) * 256 + nh * 128 + col] = v;
    }
}

// ---------------- node kernel: R10 config (measured ~33 us) ---------------------
#define NROWS 16
__global__ __launch_bounds__(256) void node_kernel(
    const float* __restrict__ bo1, const float* __restrict__ bo2,
    const float* __restrict__ Wo3, const float* __restrict__ bo3,
    float* __restrict__ outp, int stage, int step)
{
    __shared__ float s_a[NROWS][264];   // aug, later reused as h2
    __shared__ float s_h[NROWS][264];

    int r0 = blockIdx.x * NROWS;
    int t = threadIdx.x;

    for (int i = t; i < NROWS * 264; i += 256) {
        int r = i / 264, c = i % 264;
        int row = r0 + r;
        float v = 0.f;
        if (c < 4) v = g_xarg[row * 4 + c];
        else if (c < 260) v = g_agg[row * 256 + (c - 4)];
        s_a[r][c] = v;
    }
    __syncthreads();

    float acc[NROWS];

    // ---- layer 1: K=264 (zero-padded), 66 float4 steps, depth-2 prefetch
    {
        float bv = bo1[t];
        #pragma unroll
        for (int r = 0; r < NROWS; r++) acc[r] = bv;
    }
    {
        const float4* wrow = (const float4*)(g_wo1t + t * 264);
        float4 w0 = __ldg(&wrow[0]);
        float4 w1 = __ldg(&wrow[1]);
        #pragma unroll 2
        for (int it = 0; it < 66; it++) {
            float4 cw = (it & 1) ? w1 : w0;
            int jn = it + 2;
            if (jn < 66) {
                if (it & 1) w1 = __ldg(&wrow[jn]);
                else        w0 = __ldg(&wrow[jn]);
            }
            int j = it * 4;
            #pragma unroll
            for (int r = 0; r < NROWS; r++) {
                float4 a4 = *(const float4*)&s_a[r][j];
                acc[r] += a4.x * cw.x + a4.y * cw.y + a4.z * cw.z + a4.w * cw.w;
            }
        }
    }
    #pragma unroll
    for (int r = 0; r < NROWS; r++) s_h[r][t] = fmaxf(acc[r], 0.f);
    __syncthreads();

    // ---- layer 2: K=256, 64 float4 steps, depth-2 prefetch
    {
        float bv = bo2[t];
        #pragma unroll
        for (int r = 0; r < NROWS; r++) acc[r] = bv;
    }
    {
        const float4* wrow = (const float4*)(g_wo2t + t * 256);
        float4 w0 = __ldg(&wrow[0]);
        float4 w1 = __ldg(&wrow[1]);
        #pragma unroll 2
        for (int it = 0; it < 64; it++) {
            float4 cw = (it & 1) ? w1 : w0;
            int jn = it + 2;
            if (jn < 64) {
                if (it & 1) w1 = __ldg(&wrow[jn]);
                else        w0 = __ldg(&wrow[jn]);
            }
            int j = it * 4;
            #pragma unroll
            for (int r = 0; r < NROWS; r++) {
                float4 a4 = *(const float4*)&s_h[r][j];
                acc[r] += a4.x * cw.x + a4.y * cw.y + a4.z * cw.z + a4.w * cw.w;
            }
        }
    }
    __syncthreads();
    #pragma unroll
    for (int r = 0; r < NROWS; r++) s_a[r][t] = fmaxf(acc[r], 0.f);   // h2
    __syncthreads();

    // final 256->4 projection: warp w handles rows 2w, 2w+1
    int wr = t >> 5, lane = t & 31;
    #pragma unroll
    for (int rr = 0; rr < 2; rr++) {
        int rl = wr * 2 + rr;
        float4 pf = make_float4(0.f, 0.f, 0.f, 0.f);
        for (int j = lane; j < 256; j += 32) {
            float v = s_a[rl][j];
            float4 w3 = *(const float4*)(Wo3 + j * 4);
            pf.x += v * w3.x; pf.y += v * w3.y;
            pf.z += v * w3.z; pf.w += v * w3.w;
        }
        #pragma unroll
        for (int off = 16; off; off >>= 1) {
            pf.x += __shfl_xor_sync(0xffffffffu, pf.x, off);
            pf.y += __shfl_xor_sync(0xffffffffu, pf.y, off);
            pf.z += __shfl_xor_sync(0xffffffffu, pf.z, off);
            pf.w += __shfl_xor_sync(0xffffffffu, pf.w, off);
        }

        if (lane == 0) {
            int row = r0 + rl;
            float dt = (float)(step + 1) / 10.0f - (float)step / 10.0f;

            float4 xa = *(const float4*)(g_xarg + row * 4);
            float4 xs = *(const float4*)(g_xst + row * 4);

            float4 ko;
            ko.x = xa.x + pf.x + bo3[0];
            ko.y = xa.y + pf.y + bo3[1];
            ko.z = xa.z + pf.z + bo3[2];
            ko.w = xa.w + pf.w + bo3[3];

            float4 ka;
            if (stage == 0) {
                ka = ko;
            } else {
                ka = *(const float4*)(g_kacc + row * 4);
                float sc = (stage == 3) ? 1.0f : 2.0f;
                ka.x += sc * ko.x; ka.y += sc * ko.y;
                ka.z += sc * ko.z; ka.w += sc * ko.w;
            }

            if (stage < 3) {
                *(float4*)(g_kacc + row * 4) = ka;
                float cc = (stage == 2) ? dt : 0.5f * dt;
                float4 xn;
                xn.x = xs.x + cc * ko.x; xn.y = xs.y + cc * ko.y;
                xn.z = xs.z + cc * ko.z; xn.w = xs.w + cc * ko.w;
                *(float4*)(g_xarg + row * 4) = xn;
            } else {
                float cc = dt * (1.0f / 6.0f);
                float4 xn;
                xn.x = xs.x + cc * ka.x; xn.y = xs.y + cc * ka.y;
                xn.z = xs.z + cc * ka.z; xn.w = xs.w + cc * ka.w;
                *(float4*)(g_xst + row * 4) = xn;
                *(float4*)(g_xarg + row * 4) = xn;
                *(float4*)(outp + (row * NSTEP + step) * 4) = xn;
            }
        }
    }
}

// ---------------- launch ------------------------------------------------------
extern "C" void kernel_launch(void* const* d_in, const int* in_sizes, int n_in,
                              void* d_out, int out_size)
{
    const float* inputs = (const float*)d_in[0];
    const float* edges  = (const float*)d_in[1];
    const float* W1  = (const float*)d_in[4];
    const float* b1  = (const float*)d_in[5];
    const float* W2  = (const float*)d_in[6];
    const float* b2  = (const float*)d_in[7];
    const float* Wo1 = (const float*)d_in[8];
    const float* bo1 = (const float*)d_in[9];
    const float* Wo2 = (const float*)d_in[10];
    const float* bo2 = (const float*)d_in[11];
    const float* Wo3 = (const float*)d_in[12];
    const float* bo3 = (const float*)d_in[13];
    float* outp = (float*)d_out;

    cudaFuncSetAttribute(edge_mma_kernel,
                         cudaFuncAttributeMaxDynamicSharedMemorySize, SMEM_TOT);

    init_kernel<<<(BB * NN * FI + 255) / 256, 256>>>(inputs);
    w2split_kernel<<<(2 * 256 * 256) / 256, 256>>>(W2);
    wo_transpose_kernel<<<(256 * 264 + 255) / 256, 256>>>(Wo1, Wo2);

    for (int step = 0; step < NSTEP; step++) {
        for (int stage = 0; stage < 4; stage++) {
            edge_mma_kernel<<<BB * 64, 256, SMEM_TOT>>>(edges, W1, b1, b2);
            node_kernel<<<BB * NN / NROWS, 256>>>(bo1, bo2, Wo3, bo3,
                                                  outp, stage, step);
        }
    }
}